// round 1
// baseline (speedup 1.0000x reference)
#include <cuda_runtime.h>
#include <math.h>

// Problem constants
constexpr int B_  = 8;
constexpr int S_  = 1024;
constexpr int D_  = 2048;
constexpr int H_  = 16;
constexpr int G_  = 2;
constexpr int HD_ = 128;              // head dim
constexpr int REP_ = H_ / G_;         // 8
constexpr int GHD_ = G_ * HD_;        // 256
constexpr int BS_  = B_ * S_;         // 8192

// Scratch (static device globals — allocation-free)
__device__ float g_q[BS_ * D_];                    // 64 MB  (B,S,H,HD) flat
__device__ float g_k[BS_ * GHD_];                  // 8 MB   (B,S,G,HD)
__device__ float g_v[BS_ * GHD_];                  // 8 MB
__device__ float g_p[134217728];                   // 512 MB (B,H,S,S) scores/probs
__device__ float g_attn[BS_ * D_];                 // 64 MB  (B,S,H,HD)

// ---------------------------------------------------------------------------
// Tiled SGEMM core: C[M,N] = alpha * A @ (B or B^T) + bias
//   BM=BN=128, BK=8, 256 threads, 8x8 microtile per thread.
//   All dims assumed multiples of the tiles (true for every call here).
// ---------------------------------------------------------------------------
constexpr int BM = 128, BN = 128, BK = 8;

template<bool TRANSB>
__device__ __forceinline__ void gemm_tile(
    const float* __restrict__ A, const float* __restrict__ Bm,
    float* __restrict__ C, const float* __restrict__ bias,
    int K, int lda, int ldb, int ldc, float alpha)
{
    __shared__ float As[BK][BM];
    __shared__ float Bs[BK][BN];

    const int tid = threadIdx.x;
    const int tx  = tid & 15;         // 0..15 (N direction)
    const int ty  = tid >> 4;         // 0..15 (M direction)
    const int bm  = blockIdx.y * BM;
    const int bn  = blockIdx.x * BN;

    const int lrow = tid >> 1;        // 0..127
    const int lcol = (tid & 1) << 2;  // 0 or 4

    float acc[8][8];
    #pragma unroll
    for (int i = 0; i < 8; i++)
        #pragma unroll
        for (int j = 0; j < 8; j++) acc[i][j] = 0.0f;

    for (int k0 = 0; k0 < K; k0 += BK) {
        // Load A tile (128 x 8), store transposed As[k][m]
        {
            float4 av = *reinterpret_cast<const float4*>(
                A + (size_t)(bm + lrow) * lda + k0 + lcol);
            As[lcol + 0][lrow] = av.x;
            As[lcol + 1][lrow] = av.y;
            As[lcol + 2][lrow] = av.z;
            As[lcol + 3][lrow] = av.w;
        }
        if (TRANSB) {
            // B is (N x K) row-major; Bs[k][n] = B[n][k]
            float4 bv = *reinterpret_cast<const float4*>(
                Bm + (size_t)(bn + lrow) * ldb + k0 + lcol);
            Bs[lcol + 0][lrow] = bv.x;
            Bs[lcol + 1][lrow] = bv.y;
            Bs[lcol + 2][lrow] = bv.z;
            Bs[lcol + 3][lrow] = bv.w;
        } else {
            // B is (K x N) row-major
            const int br = tid >> 5;          // 0..7
            const int bc = (tid & 31) << 2;   // 0..124
            *reinterpret_cast<float4*>(&Bs[br][bc]) =
                *reinterpret_cast<const float4*>(
                    Bm + (size_t)(k0 + br) * ldb + bn + bc);
        }
        __syncthreads();

        #pragma unroll
        for (int kk = 0; kk < BK; kk++) {
            float a[8], b[8];
            *reinterpret_cast<float4*>(&a[0]) = *reinterpret_cast<const float4*>(&As[kk][ty * 8]);
            *reinterpret_cast<float4*>(&a[4]) = *reinterpret_cast<const float4*>(&As[kk][ty * 8 + 4]);
            *reinterpret_cast<float4*>(&b[0]) = *reinterpret_cast<const float4*>(&Bs[kk][tx * 8]);
            *reinterpret_cast<float4*>(&b[4]) = *reinterpret_cast<const float4*>(&Bs[kk][tx * 8 + 4]);
            #pragma unroll
            for (int i = 0; i < 8; i++)
                #pragma unroll
                for (int j = 0; j < 8; j++)
                    acc[i][j] = fmaf(a[i], b[j], acc[i][j]);
        }
        __syncthreads();
    }

    // Epilogue
    #pragma unroll
    for (int i = 0; i < 8; i++) {
        const size_t base = (size_t)(bm + ty * 8 + i) * ldc + bn + tx * 8;
        #pragma unroll
        for (int j = 0; j < 8; j += 4) {
            float4 v;
            v.x = acc[i][j + 0] * alpha;
            v.y = acc[i][j + 1] * alpha;
            v.z = acc[i][j + 2] * alpha;
            v.w = acc[i][j + 3] * alpha;
            if (bias) {
                const int nc = bn + tx * 8 + j;
                v.x += bias[nc + 0];
                v.y += bias[nc + 1];
                v.z += bias[nc + 2];
                v.w += bias[nc + 3];
            }
            *reinterpret_cast<float4*>(&C[base + j]) = v;
        }
    }
}

// ---------------------------------------------------------------------------
// Kernels
// ---------------------------------------------------------------------------

// Generic projection GEMM with bias (NN): C = A @ B + bias
__global__ void k_proj(const float* __restrict__ A, const float* __restrict__ Bm,
                       const float* __restrict__ bias, float* __restrict__ C,
                       int K, int lda, int ldb, int ldc)
{
    gemm_tile<false>(A, Bm, C, bias, K, lda, ldb, ldc, 1.0f);
}

// RoPE in place on g_q and g_k.
// One thread per (b, s, head, d<64) pair; head in [0,H) -> Q, [H,H+G) -> K.
__global__ void k_rope()
{
    const int idx = blockIdx.x * blockDim.x + threadIdx.x;
    const int total = BS_ * (H_ + G_) * (HD_ / 2);
    if (idx >= total) return;

    const int d    = idx & 63;
    const int rest = idx >> 6;
    const int head = rest % (H_ + G_);
    const int bs   = rest / (H_ + G_);
    const int s    = bs % S_;

    // inv_freq = 10000^{-d/64} = exp(-d/64 * ln(10000))
    const float inv = expf(-(float)d * (9.210340371976184f / 64.0f));
    const float f   = (float)s * inv;
    float sv, cv;
    sincosf(f, &sv, &cv);

    float* base = (head < H_)
        ? (g_q + ((size_t)bs * H_ + head) * HD_)
        : (g_k + ((size_t)bs * G_ + (head - H_)) * HD_);

    const float x1 = base[d];
    const float x2 = base[d + 64];
    base[d]      = x1 * cv - x2 * sv;
    base[d + 64] = x2 * cv + x1 * sv;
}

// Batched scores: P[z] = scale * Q_h @ K_g^T,  z = b*H + h
__global__ void k_scores(const float* __restrict__ /*unused*/)
{
    const int z = blockIdx.z;
    const int b = z / H_;
    const int h = z % H_;
    const int g = h / REP_;
    gemm_tile<true>(g_q + (size_t)b * S_ * D_ + h * HD_,
                    g_k + (size_t)b * S_ * GHD_ + g * HD_,
                    g_p + (size_t)z * S_ * S_, nullptr,
                    HD_, D_, GHD_, S_, 0.08838834764831845f);
}

// Row softmax over t (1024). One warp per row, 8 warps per block.
__global__ void k_softmax()
{
    const int row  = blockIdx.x * 8 + (threadIdx.x >> 5);
    const int lane = threadIdx.x & 31;
    float* r = g_p + (size_t)row * S_;

    float v[32];
    float mx = -INFINITY;
    #pragma unroll
    for (int i = 0; i < 32; i++) {
        v[i] = r[i * 32 + lane];
        mx = fmaxf(mx, v[i]);
    }
    #pragma unroll
    for (int o = 16; o; o >>= 1) mx = fmaxf(mx, __shfl_xor_sync(0xffffffffu, mx, o));

    float sum = 0.0f;
    #pragma unroll
    for (int i = 0; i < 32; i++) {
        v[i] = __expf(v[i] - mx);
        sum += v[i];
    }
    #pragma unroll
    for (int o = 16; o; o >>= 1) sum += __shfl_xor_sync(0xffffffffu, sum, o);

    const float inv = 1.0f / sum;
    #pragma unroll
    for (int i = 0; i < 32; i++) r[i * 32 + lane] = v[i] * inv;
}

// Batched PV: attn[b,:,h,:] = P[z] @ V_g
__global__ void k_pv()
{
    const int z = blockIdx.z;
    const int b = z / H_;
    const int h = z % H_;
    const int g = h / REP_;
    gemm_tile<false>(g_p + (size_t)z * S_ * S_,
                     g_v + (size_t)b * S_ * GHD_ + g * HD_,
                     g_attn + (size_t)b * S_ * D_ + h * HD_, nullptr,
                     S_, S_, GHD_, D_, 1.0f);
}

// ---------------------------------------------------------------------------
// Launch
// ---------------------------------------------------------------------------
extern "C" void kernel_launch(void* const* d_in, const int* /*in_sizes*/, int /*n_in*/,
                              void* d_out, int /*out_size*/)
{
    const float* x  = (const float*)d_in[0];
    const float* Wq = (const float*)d_in[1];
    const float* bq = (const float*)d_in[2];
    const float* Wk = (const float*)d_in[3];
    const float* bk = (const float*)d_in[4];
    const float* Wv = (const float*)d_in[5];
    const float* bv = (const float*)d_in[6];
    const float* Wo = (const float*)d_in[7];
    const float* bo = (const float*)d_in[8];
    float* out = (float*)d_out;

    float *pq, *pk, *pv, *pa;
    cudaGetSymbolAddress((void**)&pq, g_q);
    cudaGetSymbolAddress((void**)&pk, g_k);
    cudaGetSymbolAddress((void**)&pv, g_v);
    cudaGetSymbolAddress((void**)&pa, g_attn);

    const dim3 blk(256);

    // Projections
    k_proj<<<dim3(D_ / BN, BS_ / BM), blk>>>(x, Wq, bq, pq, D_, D_, D_, D_);
    k_proj<<<dim3(GHD_ / BN, BS_ / BM), blk>>>(x, Wk, bk, pk, D_, D_, GHD_, GHD_);
    k_proj<<<dim3(GHD_ / BN, BS_ / BM), blk>>>(x, Wv, bv, pv, D_, D_, GHD_, GHD_);

    // RoPE on Q and K
    {
        const int total = BS_ * (H_ + G_) * (HD_ / 2);
        k_rope<<<(total + 255) / 256, 256>>>();
    }

    // Attention
    k_scores<<<dim3(S_ / BN, S_ / BM, B_ * H_), blk>>>(nullptr);
    k_softmax<<<(B_ * H_ * S_) / 8, 256>>>();
    k_pv<<<dim3(HD_ / BN, S_ / BM, B_ * H_), blk>>>();

    // Output projection
    k_proj<<<dim3(D_ / BN, BS_ / BM), blk>>>(pa, Wo, bo, out, D_, D_, D_, D_);
}

// round 4
// speedup vs baseline: 1.7640x; 1.7640x over previous
#include <cuda_runtime.h>
#include <math.h>
#include <stdint.h>

// Problem constants
constexpr int B_  = 8;
constexpr int S_  = 1024;
constexpr int D_  = 2048;
constexpr int H_  = 16;
constexpr int G_  = 2;
constexpr int HD_ = 128;
constexpr int REP_ = H_ / G_;         // 8
constexpr int GHD_ = G_ * HD_;        // 256
constexpr int BS_  = B_ * S_;         // 8192

// Scratch
__device__ float g_q[BS_ * D_];
__device__ float g_k[BS_ * GHD_];
__device__ float g_v[BS_ * GHD_];
__device__ float g_p[(size_t)B_ * H_ * S_ * S_];   // 512 MB
__device__ float g_attn[BS_ * D_];

// ---------------------------------------------------------------------------
// 3xTF32 tensor-core GEMM: C[M,N] = alpha * A @ (B or B^T) (+ bias)
//   128x128 block, BK=16, 256 thr (8 warps 4x2), warp tile 32x64,
//   m16n8k8 tf32 mma with hi/lo operand splitting (fp32-accurate),
//   cp.async double-buffered smem.
// ---------------------------------------------------------------------------
constexpr int BM = 128, BN = 128, BK = 16;
constexpr int LDA  = BK + 4;     // 20  -> bank(g*20+t) all-distinct
constexpr int LDBN = BN + 8;     // 136 -> bank(t*8+g)  all-distinct
constexpr int A_SZ = BM * LDA;   // 2560 floats
constexpr int B_SZ = 2560;
constexpr int BUF  = A_SZ + B_SZ;

__device__ __forceinline__ void cpasync16(float* dst_smem, const float* src) {
    uint32_t d = (uint32_t)__cvta_generic_to_shared(dst_smem);
    asm volatile("cp.async.cg.shared.global [%0], [%1], 16;" :: "r"(d), "l"(src));
}

__device__ __forceinline__ void mma_tf32(float (&d)[4], const uint32_t (&a)[4],
                                         const uint32_t (&b)[2]) {
    asm volatile(
        "mma.sync.aligned.m16n8k8.row.col.f32.tf32.tf32.f32 "
        "{%0,%1,%2,%3}, {%4,%5,%6,%7}, {%8,%9}, {%0,%1,%2,%3};"
        : "+f"(d[0]), "+f"(d[1]), "+f"(d[2]), "+f"(d[3])
        : "r"(a[0]), "r"(a[1]), "r"(a[2]), "r"(a[3]), "r"(b[0]), "r"(b[1]));
}

// hi = top bits (exact tf32), lo = exact residual (mma truncates it to tf32)
__device__ __forceinline__ void split_tf32(float v, uint32_t& hi, uint32_t& lo) {
    uint32_t u = __float_as_uint(v) & 0xFFFFE000u;
    hi = u;
    lo = __float_as_uint(v - __uint_as_float(u));
}

template<bool TRANSB, bool BIAS>
__device__ __forceinline__ void gemm_mma(
    const float* __restrict__ A, const float* __restrict__ Bm,
    float* __restrict__ C, const float* __restrict__ bias,
    int K, int lda, int ldb, int ldc, float alpha)
{
    __shared__ float sm[2 * BUF];

    const int tid  = threadIdx.x;
    const int warp = tid >> 5;
    const int lane = tid & 31;
    const int g    = lane >> 2;       // 0..7
    const int t    = lane & 3;        // 0..3
    const int wm   = (warp >> 1) * 32;
    const int wn   = (warp & 1) * 64;
    const int bm   = blockIdx.y * BM;
    const int bn   = blockIdx.x * BN;

    float acc[2][8][4] = {};

    const int NIT = K / BK;

    auto load_tile = [&](int bi, int k0) {
        float* as = sm + bi * BUF;
        float* bs = as + A_SZ;
        #pragma unroll
        for (int r = 0; r < 2; r++) {                 // A: 128x16
            int i   = tid + r * 256;
            int row = i >> 2;
            int c4  = (i & 3) * 4;
            cpasync16(as + row * LDA + c4, A + (size_t)(bm + row) * lda + k0 + c4);
        }
        if (TRANSB) {
            #pragma unroll
            for (int r = 0; r < 2; r++) {
                int i   = tid + r * 256;
                int row = i >> 2;
                int c4  = (i & 3) * 4;
                cpasync16(bs + row * LDA + c4, Bm + (size_t)(bn + row) * ldb + k0 + c4);
            }
        } else {
            #pragma unroll
            for (int r = 0; r < 2; r++) {
                int i   = tid + r * 256;
                int row = i >> 5;
                int c4  = (i & 31) * 4;
                cpasync16(bs + row * LDBN + c4, Bm + (size_t)(k0 + row) * ldb + bn + c4);
            }
        }
        asm volatile("cp.async.commit_group;");
    };

    load_tile(0, 0);

    for (int it = 0; it < NIT; it++) {
        if (it + 1 < NIT) {
            load_tile((it + 1) & 1, (it + 1) * BK);
            asm volatile("cp.async.wait_group 1;");
        } else {
            asm volatile("cp.async.wait_group 0;");
        }
        __syncthreads();

        const float* as = sm + (it & 1) * BUF;
        const float* bs = as + A_SZ;

        #pragma unroll
        for (int kk = 0; kk < 2; kk++) {
            const int k0 = kk * 8;
            uint32_t ah[2][4], al[2][4];
            #pragma unroll
            for (int mt = 0; mt < 2; mt++) {
                const float* ab = as + (wm + mt * 16 + g) * LDA + k0 + t;
                split_tf32(ab[0],           ah[mt][0], al[mt][0]);
                split_tf32(ab[8 * LDA],     ah[mt][1], al[mt][1]);
                split_tf32(ab[4],           ah[mt][2], al[mt][2]);
                split_tf32(ab[8 * LDA + 4], ah[mt][3], al[mt][3]);
            }
            #pragma unroll
            for (int nt = 0; nt < 8; nt++) {
                uint32_t bh[2], bl[2];
                if (TRANSB) {
                    const float* bb = bs + (wn + nt * 8 + g) * LDA + k0 + t;
                    split_tf32(bb[0], bh[0], bl[0]);
                    split_tf32(bb[4], bh[1], bl[1]);
                } else {
                    const float* bb = bs + (k0 + t) * LDBN + wn + nt * 8 + g;
                    split_tf32(bb[0],        bh[0], bl[0]);
                    split_tf32(bb[4 * LDBN], bh[1], bl[1]);
                }
                #pragma unroll
                for (int mt = 0; mt < 2; mt++) {
                    mma_tf32(acc[mt][nt], ah[mt], bh);   // hi*hi
                    mma_tf32(acc[mt][nt], al[mt], bh);   // lo*hi
                    mma_tf32(acc[mt][nt], ah[mt], bl);   // hi*lo
                }
            }
        }
        __syncthreads();
    }

    // Epilogue
    #pragma unroll
    for (int mt = 0; mt < 2; mt++) {
        const int row0 = bm + wm + mt * 16 + g;
        #pragma unroll
        for (int nt = 0; nt < 8; nt++) {
            const int col = bn + wn + nt * 8 + 2 * t;
            float bx = 0.f, by = 0.f;
            if (BIAS) { bx = bias[col]; by = bias[col + 1]; }
            float2 v0 = { acc[mt][nt][0] * alpha + bx, acc[mt][nt][1] * alpha + by };
            float2 v1 = { acc[mt][nt][2] * alpha + bx, acc[mt][nt][3] * alpha + by };
            *reinterpret_cast<float2*>(C + (size_t)row0       * ldc + col) = v0;
            *reinterpret_cast<float2*>(C + (size_t)(row0 + 8) * ldc + col) = v1;
        }
    }
}

// ---------------------------------------------------------------------------
// Kernels
// ---------------------------------------------------------------------------
__global__ void __launch_bounds__(256, 2)
k_proj(const float* __restrict__ A, const float* __restrict__ Bm,
       const float* __restrict__ bias, float* __restrict__ C,
       int K, int lda, int ldb, int ldc)
{
    gemm_mma<false, true>(A, Bm, C, bias, K, lda, ldb, ldc, 1.0f);
}

__global__ void __launch_bounds__(256, 2) k_scores()
{
    const int z = blockIdx.z;
    const int b = z / H_;
    const int h = z % H_;
    const int g = h / REP_;
    gemm_mma<true, false>(g_q + (size_t)b * S_ * D_ + h * HD_,
                          g_k + (size_t)b * S_ * GHD_ + g * HD_,
                          g_p + (size_t)z * S_ * S_, nullptr,
                          HD_, D_, GHD_, S_, 0.08838834764831845f);
}

__global__ void __launch_bounds__(256, 2) k_pv()
{
    const int z = blockIdx.z;
    const int b = z / H_;
    const int h = z % H_;
    const int g = h / REP_;
    gemm_mma<false, false>(g_p + (size_t)z * S_ * S_,
                           g_v + (size_t)b * S_ * GHD_ + g * HD_,
                           g_attn + (size_t)b * S_ * D_ + h * HD_, nullptr,
                           S_, S_, GHD_, D_, 1.0f);
}

// RoPE in place on g_q and g_k
__global__ void k_rope()
{
    const int idx = blockIdx.x * blockDim.x + threadIdx.x;
    const int total = BS_ * (H_ + G_) * (HD_ / 2);
    if (idx >= total) return;

    const int d    = idx & 63;
    const int rest = idx >> 6;
    const int head = rest % (H_ + G_);
    const int bs   = rest / (H_ + G_);
    const int s    = bs % S_;

    const float inv = expf(-(float)d * (9.210340371976184f / 64.0f));
    float sv, cv;
    sincosf((float)s * inv, &sv, &cv);

    float* base = (head < H_)
        ? (g_q + ((size_t)bs * H_ + head) * HD_)
        : (g_k + ((size_t)bs * G_ + (head - H_)) * HD_);

    const float x1 = base[d];
    const float x2 = base[d + 64];
    base[d]      = x1 * cv - x2 * sv;
    base[d + 64] = x2 * cv + x1 * sv;
}

// Row softmax over t (1024). One warp per row.
__global__ void k_softmax()
{
    const int row  = blockIdx.x * 8 + (threadIdx.x >> 5);
    const int lane = threadIdx.x & 31;
    float* r = g_p + (size_t)row * S_;

    float v[32];
    float mx = -INFINITY;
    #pragma unroll
    for (int i = 0; i < 32; i++) {
        v[i] = r[i * 32 + lane];
        mx = fmaxf(mx, v[i]);
    }
    #pragma unroll
    for (int o = 16; o; o >>= 1) mx = fmaxf(mx, __shfl_xor_sync(0xffffffffu, mx, o));

    float sum = 0.0f;
    #pragma unroll
    for (int i = 0; i < 32; i++) {
        v[i] = __expf(v[i] - mx);
        sum += v[i];
    }
    #pragma unroll
    for (int o = 16; o; o >>= 1) sum += __shfl_xor_sync(0xffffffffu, sum, o);

    const float inv = 1.0f / sum;
    #pragma unroll
    for (int i = 0; i < 32; i++) r[i * 32 + lane] = v[i] * inv;
}

// ---------------------------------------------------------------------------
// Launch
// ---------------------------------------------------------------------------
extern "C" void kernel_launch(void* const* d_in, const int* /*in_sizes*/, int /*n_in*/,
                              void* d_out, int /*out_size*/)
{
    const float* x  = (const float*)d_in[0];
    const float* Wq = (const float*)d_in[1];
    const float* bq = (const float*)d_in[2];
    const float* Wk = (const float*)d_in[3];
    const float* bk = (const float*)d_in[4];
    const float* Wv = (const float*)d_in[5];
    const float* bv = (const float*)d_in[6];
    const float* Wo = (const float*)d_in[7];
    const float* bo = (const float*)d_in[8];
    float* out = (float*)d_out;

    float *pq, *pk, *pv, *pa;
    cudaGetSymbolAddress((void**)&pq, g_q);
    cudaGetSymbolAddress((void**)&pk, g_k);
    cudaGetSymbolAddress((void**)&pv, g_v);
    cudaGetSymbolAddress((void**)&pa, g_attn);

    const dim3 blk(256);

    // Projections
    k_proj<<<dim3(D_ / BN,   BS_ / BM), blk>>>(x, Wq, bq, pq, D_, D_, D_,   D_);
    k_proj<<<dim3(GHD_ / BN, BS_ / BM), blk>>>(x, Wk, bk, pk, D_, D_, GHD_, GHD_);
    k_proj<<<dim3(GHD_ / BN, BS_ / BM), blk>>>(x, Wv, bv, pv, D_, D_, GHD_, GHD_);

    // RoPE
    {
        const int total = BS_ * (H_ + G_) * (HD_ / 2);
        k_rope<<<(total + 255) / 256, 256>>>();
    }

    // Attention
    k_scores<<<dim3(S_ / BN, S_ / BM, B_ * H_), blk>>>();
    k_softmax<<<(B_ * H_ * S_) / 8, 256>>>();
    k_pv<<<dim3(HD_ / BN, S_ / BM, B_ * H_), blk>>>();

    // Output projection
    k_proj<<<dim3(D_ / BN, BS_ / BM), blk>>>(pa, Wo, bo, out, D_, D_, D_, D_);
}

// round 6
// speedup vs baseline: 1.7925x; 1.0161x over previous
#include <cuda_runtime.h>
#include <math.h>
#include <stdint.h>

// Problem constants
constexpr int B_  = 8;
constexpr int S_  = 1024;
constexpr int D_  = 2048;
constexpr int H_  = 16;
constexpr int G_  = 2;
constexpr int HD_ = 128;
constexpr int REP_ = H_ / G_;         // 8
constexpr int GHD_ = G_ * HD_;        // 256
constexpr int BS_  = B_ * S_;         // 8192

// Scratch
__device__ float g_q[BS_ * D_];
__device__ float g_k[BS_ * GHD_];
__device__ float g_v[BS_ * GHD_];
__device__ float g_p[(size_t)B_ * H_ * S_ * S_];   // 512 MB
__device__ float g_attn[BS_ * D_];

// ---------------------------------------------------------------------------
// 3xTF32 tensor-core GEMM, dependency-unrolled:
//   per k-step, three sweeps (hi*hi, lo*hi, hi*lo) over all 16 fragments so
//   same-accumulator MMAs are 16 issues apart (no RAW stall on the HMMA pipe).
// ---------------------------------------------------------------------------
constexpr int BM = 128, BN = 128, BK = 16;
constexpr int LDA  = BK + 4;     // 20
constexpr int LDBN = BN + 8;     // 136
constexpr int A_SZ = BM * LDA;   // 2560 floats
constexpr int B_SZ = 2560;
constexpr int BUF  = A_SZ + B_SZ;

__device__ __forceinline__ void cpasync16(float* dst_smem, const float* src) {
    uint32_t d = (uint32_t)__cvta_generic_to_shared(dst_smem);
    asm volatile("cp.async.cg.shared.global [%0], [%1], 16;" :: "r"(d), "l"(src));
}

__device__ __forceinline__ void mma_tf32(float (&d)[4], const uint32_t (&a)[4],
                                         const uint32_t (&b)[2]) {
    asm volatile(
        "mma.sync.aligned.m16n8k8.row.col.f32.tf32.tf32.f32 "
        "{%0,%1,%2,%3}, {%4,%5,%6,%7}, {%8,%9}, {%0,%1,%2,%3};"
        : "+f"(d[0]), "+f"(d[1]), "+f"(d[2]), "+f"(d[3])
        : "r"(a[0]), "r"(a[1]), "r"(a[2]), "r"(a[3]), "r"(b[0]), "r"(b[1]));
}

__device__ __forceinline__ uint32_t hi_bits(uint32_t u) { return u & 0xFFFFE000u; }
__device__ __forceinline__ uint32_t lo_bits(uint32_t u) {
    return __float_as_uint(__uint_as_float(u) - __uint_as_float(u & 0xFFFFE000u));
}

template<bool TRANSB, bool BIAS>
__device__ __forceinline__ void gemm_mma(
    const float* __restrict__ A, const float* __restrict__ Bm,
    float* __restrict__ C, const float* __restrict__ bias,
    int K, int lda, int ldb, int ldc, float alpha)
{
    __shared__ float sm[2 * BUF];

    const int tid  = threadIdx.x;
    const int warp = tid >> 5;
    const int lane = tid & 31;
    const int g    = lane >> 2;
    const int t    = lane & 3;
    const int wm   = (warp >> 1) * 32;
    const int wn   = (warp & 1) * 64;
    const int bm   = blockIdx.y * BM;
    const int bn   = blockIdx.x * BN;

    float acc[2][8][4] = {};

    const int NIT = K / BK;

    auto load_tile = [&](int bi, int k0) {
        float* as = sm + bi * BUF;
        float* bs = as + A_SZ;
        #pragma unroll
        for (int r = 0; r < 2; r++) {
            int i   = tid + r * 256;
            int row = i >> 2;
            int c4  = (i & 3) * 4;
            cpasync16(as + row * LDA + c4, A + (size_t)(bm + row) * lda + k0 + c4);
        }
        if (TRANSB) {
            #pragma unroll
            for (int r = 0; r < 2; r++) {
                int i   = tid + r * 256;
                int row = i >> 2;
                int c4  = (i & 3) * 4;
                cpasync16(bs + row * LDA + c4, Bm + (size_t)(bn + row) * ldb + k0 + c4);
            }
        } else {
            #pragma unroll
            for (int r = 0; r < 2; r++) {
                int i   = tid + r * 256;
                int row = i >> 5;
                int c4  = (i & 31) * 4;
                cpasync16(bs + row * LDBN + c4, Bm + (size_t)(k0 + row) * ldb + bn + c4);
            }
        }
        asm volatile("cp.async.commit_group;");
    };

    load_tile(0, 0);

    for (int it = 0; it < NIT; it++) {
        if (it + 1 < NIT) {
            load_tile((it + 1) & 1, (it + 1) * BK);
            asm volatile("cp.async.wait_group 1;");
        } else {
            asm volatile("cp.async.wait_group 0;");
        }
        __syncthreads();

        const float* as = sm + (it & 1) * BUF;
        const float* bs = as + A_SZ;

        #pragma unroll
        for (int kk = 0; kk < 2; kk++) {
            const int k0 = kk * 8;

            // A fragments: raw + split
            uint32_t araw[2][4], ah[2][4], al[2][4];
            #pragma unroll
            for (int mt = 0; mt < 2; mt++) {
                const float* ab = as + (wm + mt * 16 + g) * LDA + k0 + t;
                araw[mt][0] = __float_as_uint(ab[0]);
                araw[mt][1] = __float_as_uint(ab[8 * LDA]);
                araw[mt][2] = __float_as_uint(ab[4]);
                araw[mt][3] = __float_as_uint(ab[8 * LDA + 4]);
                #pragma unroll
                for (int i = 0; i < 4; i++) {
                    ah[mt][i] = hi_bits(araw[mt][i]);
                    al[mt][i] = lo_bits(araw[mt][i]);
                }
            }

            // B fragments: raw only (split per sweep to save registers)
            uint32_t braw[8][2];
            #pragma unroll
            for (int nt = 0; nt < 8; nt++) {
                if (TRANSB) {
                    const float* bb = bs + (wn + nt * 8 + g) * LDA + k0 + t;
                    braw[nt][0] = __float_as_uint(bb[0]);
                    braw[nt][1] = __float_as_uint(bb[4]);
                } else {
                    const float* bb = bs + (k0 + t) * LDBN + wn + nt * 8 + g;
                    braw[nt][0] = __float_as_uint(bb[0]);
                    braw[nt][1] = __float_as_uint(bb[4 * LDBN]);
                }
            }

            // Sweep 1: hi*hi (16 independent MMAs)
            #pragma unroll
            for (int nt = 0; nt < 8; nt++) {
                uint32_t bh[2] = { hi_bits(braw[nt][0]), hi_bits(braw[nt][1]) };
                mma_tf32(acc[0][nt], ah[0], bh);
                mma_tf32(acc[1][nt], ah[1], bh);
            }
            // Sweep 2: lo*hi
            #pragma unroll
            for (int nt = 0; nt < 8; nt++) {
                uint32_t bh[2] = { hi_bits(braw[nt][0]), hi_bits(braw[nt][1]) };
                mma_tf32(acc[0][nt], al[0], bh);
                mma_tf32(acc[1][nt], al[1], bh);
            }
            // Sweep 3: hi*lo
            #pragma unroll
            for (int nt = 0; nt < 8; nt++) {
                uint32_t bl[2] = { lo_bits(braw[nt][0]), lo_bits(braw[nt][1]) };
                mma_tf32(acc[0][nt], ah[0], bl);
                mma_tf32(acc[1][nt], ah[1], bl);
            }
        }
        __syncthreads();
    }

    // Epilogue
    #pragma unroll
    for (int mt = 0; mt < 2; mt++) {
        const int row0 = bm + wm + mt * 16 + g;
        #pragma unroll
        for (int nt = 0; nt < 8; nt++) {
            const int col = bn + wn + nt * 8 + 2 * t;
            float bx = 0.f, by = 0.f;
            if (BIAS) { bx = bias[col]; by = bias[col + 1]; }
            float2 v0 = { acc[mt][nt][0] * alpha + bx, acc[mt][nt][1] * alpha + by };
            float2 v1 = { acc[mt][nt][2] * alpha + bx, acc[mt][nt][3] * alpha + by };
            *reinterpret_cast<float2*>(C + (size_t)row0       * ldc + col) = v0;
            *reinterpret_cast<float2*>(C + (size_t)(row0 + 8) * ldc + col) = v1;
        }
    }
}

// ---------------------------------------------------------------------------
// Kernels
// ---------------------------------------------------------------------------
__global__ void __launch_bounds__(256, 2)
k_proj(const float* __restrict__ A, const float* __restrict__ Bm,
       const float* __restrict__ bias, float* __restrict__ C,
       int K, int lda, int ldb, int ldc)
{
    gemm_mma<false, true>(A, Bm, C, bias, K, lda, ldb, ldc, 1.0f);
}

__global__ void __launch_bounds__(256, 2) k_scores()
{
    const int z = blockIdx.z;
    const int b = z / H_;
    const int h = z % H_;
    const int g = h / REP_;
    gemm_mma<true, false>(g_q + (size_t)b * S_ * D_ + h * HD_,
                          g_k + (size_t)b * S_ * GHD_ + g * HD_,
                          g_p + (size_t)z * S_ * S_, nullptr,
                          HD_, D_, GHD_, S_, 0.08838834764831845f);
}

__global__ void __launch_bounds__(256, 2) k_pv()
{
    const int z = blockIdx.z;
    const int b = z / H_;
    const int h = z % H_;
    const int g = h / REP_;
    gemm_mma<false, false>(g_p + (size_t)z * S_ * S_,
                           g_v + (size_t)b * S_ * GHD_ + g * HD_,
                           g_attn + (size_t)b * S_ * D_ + h * HD_, nullptr,
                           S_, S_, GHD_, D_, 1.0f);
}

// RoPE in place on g_q and g_k
__global__ void k_rope()
{
    const int idx = blockIdx.x * blockDim.x + threadIdx.x;
    const int total = BS_ * (H_ + G_) * (HD_ / 2);
    if (idx >= total) return;

    const int d    = idx & 63;
    const int rest = idx >> 6;
    const int head = rest % (H_ + G_);
    const int bs   = rest / (H_ + G_);
    const int s    = bs % S_;

    const float inv = expf(-(float)d * (9.210340371976184f / 64.0f));
    float sv, cv;
    sincosf((float)s * inv, &sv, &cv);

    float* base = (head < H_)
        ? (g_q + ((size_t)bs * H_ + head) * HD_)
        : (g_k + ((size_t)bs * G_ + (head - H_)) * HD_);

    const float x1 = base[d];
    const float x2 = base[d + 64];
    base[d]      = x1 * cv - x2 * sv;
    base[d + 64] = x2 * cv + x1 * sv;
}

// Row softmax over t (1024). One warp per row.
__global__ void k_softmax()
{
    const int row  = blockIdx.x * 8 + (threadIdx.x >> 5);
    const int lane = threadIdx.x & 31;
    float* r = g_p + (size_t)row * S_;

    float v[32];
    float mx = -INFINITY;
    #pragma unroll
    for (int i = 0; i < 32; i++) {
        v[i] = r[i * 32 + lane];
        mx = fmaxf(mx, v[i]);
    }
    #pragma unroll
    for (int o = 16; o; o >>= 1) mx = fmaxf(mx, __shfl_xor_sync(0xffffffffu, mx, o));

    float sum = 0.0f;
    #pragma unroll
    for (int i = 0; i < 32; i++) {
        v[i] = __expf(v[i] - mx);
        sum += v[i];
    }
    #pragma unroll
    for (int o = 16; o; o >>= 1) sum += __shfl_xor_sync(0xffffffffu, sum, o);

    const float inv = 1.0f / sum;
    #pragma unroll
    for (int i = 0; i < 32; i++) r[i * 32 + lane] = v[i] * inv;
}

// ---------------------------------------------------------------------------
// Launch
// ---------------------------------------------------------------------------
extern "C" void kernel_launch(void* const* d_in, const int* /*in_sizes*/, int /*n_in*/,
                              void* d_out, int /*out_size*/)
{
    const float* x  = (const float*)d_in[0];
    const float* Wq = (const float*)d_in[1];
    const float* bq = (const float*)d_in[2];
    const float* Wk = (const float*)d_in[3];
    const float* bk = (const float*)d_in[4];
    const float* Wv = (const float*)d_in[5];
    const float* bv = (const float*)d_in[6];
    const float* Wo = (const float*)d_in[7];
    const float* bo = (const float*)d_in[8];
    float* out = (float*)d_out;

    float *pq, *pk, *pv, *pa;
    cudaGetSymbolAddress((void**)&pq, g_q);
    cudaGetSymbolAddress((void**)&pk, g_k);
    cudaGetSymbolAddress((void**)&pv, g_v);
    cudaGetSymbolAddress((void**)&pa, g_attn);

    const dim3 blk(256);

    // Projections
    k_proj<<<dim3(D_ / BN,   BS_ / BM), blk>>>(x, Wq, bq, pq, D_, D_, D_,   D_);
    k_proj<<<dim3(GHD_ / BN, BS_ / BM), blk>>>(x, Wk, bk, pk, D_, D_, GHD_, GHD_);
    k_proj<<<dim3(GHD_ / BN, BS_ / BM), blk>>>(x, Wv, bv, pv, D_, D_, GHD_, GHD_);

    // RoPE
    {
        const int total = BS_ * (H_ + G_) * (HD_ / 2);
        k_rope<<<(total + 255) / 256, 256>>>();
    }

    // Attention
    k_scores<<<dim3(S_ / BN, S_ / BM, B_ * H_), blk>>>();
    k_softmax<<<(B_ * H_ * S_) / 8, 256>>>();
    k_pv<<<dim3(HD_ / BN, S_ / BM, B_ * H_), blk>>>();

    // Output projection
    k_proj<<<dim3(D_ / BN, BS_ / BM), blk>>>(pa, Wo, bo, out, D_, D_, D_, D_);
}